// round 10
// baseline (speedup 1.0000x reference)
#include <cuda_runtime.h>
#include <cuda_bf16.h>

#define B_ROWS 8192
#define ITEM_NUM 10000
#define THREADS 256
#define GROUP_ROWS 128
#define NGROUPS (B_ROWS / GROUP_ROWS)   /* 64 */

// Scratch (no cudaMalloc allowed). Zero-initialized at module load;
// counters are reset by their last user each launch (graph-replay safe).
__device__ float g_row_loss[B_ROWS];
__device__ float g_partial[NGROUPS];
__device__ unsigned int g_cnt[NGROUPS];
__device__ unsigned int g_done;

__global__ __launch_bounds__(THREADS)
void dq_fused_kernel(const float* __restrict__ hs,
                     const float* __restrict__ tq,
                     const float* __restrict__ rewards,
                     const float* __restrict__ discount,
                     const unsigned char* __restrict__ is_done,
                     const float* __restrict__ W,
                     const float* __restrict__ bias,
                     float* __restrict__ out) {
    const int row = blockIdx.x;
    const int grp = row / GROUP_ROWS;
    const float4* __restrict__ hsr = reinterpret_cast<const float4*>(hs + (size_t)row * ITEM_NUM);
    const float4* __restrict__ tqr = reinterpret_cast<const float4*>(tq + (size_t)row * ITEM_NUM);
    const float4* __restrict__ w4  = reinterpret_cast<const float4*>(W);
    const int n4 = ITEM_NUM / 4;  // 2500

    float qs = 0.0f, ns = 0.0f;
    for (int i = threadIdx.x; i < n4; i += THREADS) {
        float4 w = w4[i];
        float4 h = hsr[i];
        float4 t = tqr[i];
        qs = fmaf(h.x, w.x, qs); qs = fmaf(h.y, w.y, qs);
        qs = fmaf(h.z, w.z, qs); qs = fmaf(h.w, w.w, qs);
        ns = fmaf(t.x, w.x, ns); ns = fmaf(t.y, w.y, ns);
        ns = fmaf(t.z, w.z, ns); ns = fmaf(t.w, w.w, ns);
    }

    // Warp reduce both sums
    #pragma unroll
    for (int off = 16; off > 0; off >>= 1) {
        qs += __shfl_down_sync(0xFFFFFFFFu, qs, off);
        ns += __shfl_down_sync(0xFFFFFFFFu, ns, off);
    }

    __shared__ float sq[THREADS / 32];
    __shared__ float sn[THREADS / 32];
    __shared__ bool  s_group_last;
    const int lane = threadIdx.x & 31;
    const int wid  = threadIdx.x >> 5;
    if (lane == 0) { sq[wid] = qs; sn[wid] = ns; }
    __syncthreads();

    if (threadIdx.x == 0) {
        float q = 0.0f, n = 0.0f;
        #pragma unroll
        for (int w = 0; w < THREADS / 32; w++) { q += sq[w]; n += sn[w]; }
        const float b = bias[0];
        const float qv  = fmaxf(q + b, 0.0f);
        const float nqv = fmaxf(n + b, 0.0f);
        const float ps  = fabsf(rewards[row] + discount[0] * nqv - qv);
        g_row_loss[row] = is_done[row] ? 0.0f : ps;
        // Release-ordered arrival on the per-group counter.
        unsigned int prev;
        asm volatile("atom.add.release.gpu.u32 %0, [%1], %2;"
                     : "=r"(prev)
                     : "l"(&g_cnt[grp]), "r"(1u)
                     : "memory");
        s_group_last = (prev == GROUP_ROWS - 1u);
    }
    __syncthreads();

    if (s_group_last) {
        // Group-level reduction: runs mid-kernel, overlapped with other groups.
        // Fixed mapping + fixed tree => deterministic. __ldcg: L2-coherent.
        __shared__ float s[THREADS];
        float v = 0.0f;
        if (threadIdx.x < GROUP_ROWS)
            v = __ldcg(&g_row_loss[grp * GROUP_ROWS + threadIdx.x]);
        s[threadIdx.x] = v;
        __syncthreads();
        #pragma unroll
        for (int st = THREADS / 2; st > 0; st >>= 1) {
            if (threadIdx.x < st) s[threadIdx.x] += s[threadIdx.x + st];
            __syncthreads();
        }
        if (threadIdx.x == 0) {
            g_partial[grp] = s[0];
            g_cnt[grp] = 0;  // reset for next graph replay
            unsigned int prevd;
            asm volatile("atom.add.release.gpu.u32 %0, [%1], %2;"
                         : "=r"(prevd)
                         : "l"(&g_done), "r"(1u)
                         : "memory");
            if (prevd == NGROUPS - 1u) {
                // Final: fixed-order sum of 64 partials (single thread, tiny).
                __threadfence();  // acquire side, one CTA only
                const float4* p4 = reinterpret_cast<const float4*>(g_partial);
                float total = 0.0f;
                #pragma unroll
                for (int i = 0; i < NGROUPS / 4; i++) {
                    float4 v4 = __ldcg(&p4[i]);
                    total += ((v4.x + v4.y) + (v4.z + v4.w));
                }
                out[0] = total / (float)B_ROWS;
                g_done = 0;  // reset for next graph replay
            }
        }
    }
}

extern "C" void kernel_launch(void* const* d_in, const int* in_sizes, int n_in,
                              void* d_out, int out_size) {
    const float*         hs       = (const float*)d_in[0];
    // d_in[1] = actions (unused by reference)
    const float*         rewards  = (const float*)d_in[2];
    const float*         discount = (const float*)d_in[3];
    const float*         tq       = (const float*)d_in[4];
    const unsigned char* is_done  = (const unsigned char*)d_in[5];
    const float*         W        = (const float*)d_in[6];
    const float*         bias     = (const float*)d_in[7];
    float* out = (float*)d_out;

    dq_fused_kernel<<<B_ROWS, THREADS>>>(hs, tq, rewards, discount, is_done, W, bias, out);
}

// round 12
// speedup vs baseline: 1.0269x; 1.0269x over previous
#include <cuda_runtime.h>
#include <cuda_bf16.h>

#define B_ROWS 8192
#define ITEM_NUM 10000
#define THREADS 256
#define FP_SCALE 4294967296.0   /* 2^32 fixed-point scale */

// Scratch (no cudaMalloc allowed). Winner resets both each launch (replay-safe).
__device__ unsigned long long g_sum = 0ull;
__device__ unsigned int g_arrived = 0u;

__global__ __launch_bounds__(THREADS)
void dq_fused_kernel(const float* __restrict__ hs,
                     const float* __restrict__ tq,
                     const float* __restrict__ rewards,
                     const float* __restrict__ discount,
                     const unsigned char* __restrict__ is_done,
                     const float* __restrict__ W,
                     const float* __restrict__ bias,
                     float* __restrict__ out) {
    const int row = blockIdx.x;
    const float4* __restrict__ hsr = reinterpret_cast<const float4*>(hs + (size_t)row * ITEM_NUM);
    const float4* __restrict__ tqr = reinterpret_cast<const float4*>(tq + (size_t)row * ITEM_NUM);
    const float4* __restrict__ w4  = reinterpret_cast<const float4*>(W);
    const int n4 = ITEM_NUM / 4;  // 2500

    float qs = 0.0f, ns = 0.0f;
    for (int i = threadIdx.x; i < n4; i += THREADS) {
        float4 w = w4[i];
        float4 h = hsr[i];
        float4 t = tqr[i];
        qs = fmaf(h.x, w.x, qs); qs = fmaf(h.y, w.y, qs);
        qs = fmaf(h.z, w.z, qs); qs = fmaf(h.w, w.w, qs);
        ns = fmaf(t.x, w.x, ns); ns = fmaf(t.y, w.y, ns);
        ns = fmaf(t.z, w.z, ns); ns = fmaf(t.w, w.w, ns);
    }

    // Warp reduce both sums
    #pragma unroll
    for (int off = 16; off > 0; off >>= 1) {
        qs += __shfl_down_sync(0xFFFFFFFFu, qs, off);
        ns += __shfl_down_sync(0xFFFFFFFFu, ns, off);
    }

    __shared__ float sq[THREADS / 32];
    __shared__ float sn[THREADS / 32];
    const int lane = threadIdx.x & 31;
    const int wid  = threadIdx.x >> 5;
    if (lane == 0) { sq[wid] = qs; sn[wid] = ns; }
    __syncthreads();

    if (threadIdx.x == 0) {
        float q = 0.0f, n = 0.0f;
        #pragma unroll
        for (int w = 0; w < THREADS / 32; w++) { q += sq[w]; n += sn[w]; }
        const float b = bias[0];
        const float qv  = fmaxf(q + b, 0.0f);
        const float nqv = fmaxf(n + b, 0.0f);
        float ps = fabsf(rewards[row] + discount[0] * nqv - qv);
        if (is_done[row]) ps = 0.0f;

        // Deterministic accumulation: fixed-point u64 atomic (associative).
        const unsigned long long q64 = (unsigned long long)((double)ps * FP_SCALE);
        atomicAdd(&g_sum, q64);

        // Release-ordered arrival; winner finalizes.
        unsigned int prev;
        asm volatile("atom.add.release.gpu.u32 %0, [%1], %2;"
                     : "=r"(prev)
                     : "l"(&g_arrived), "r"(1u)
                     : "memory");
        if (prev == (unsigned int)(gridDim.x - 1)) {
            __threadfence();  // acquire: all g_sum contributions visible
            unsigned long long total = atomicAdd(&g_sum, 0ull);  // atomic read
            out[0] = (float)((double)total / FP_SCALE / (double)B_ROWS);
            g_sum = 0ull;       // reset for next graph replay
            __threadfence();
            g_arrived = 0u;
        }
    }
}

extern "C" void kernel_launch(void* const* d_in, const int* in_sizes, int n_in,
                              void* d_out, int out_size) {
    const float*         hs       = (const float*)d_in[0];
    // d_in[1] = actions (unused by reference)
    const float*         rewards  = (const float*)d_in[2];
    const float*         discount = (const float*)d_in[3];
    const float*         tq       = (const float*)d_in[4];
    const unsigned char* is_done  = (const unsigned char*)d_in[5];
    const float*         W        = (const float*)d_in[6];
    const float*         bias     = (const float*)d_in[7];
    float* out = (float*)d_out;

    dq_fused_kernel<<<B_ROWS, THREADS>>>(hs, tq, rewards, discount, is_done, W, bias, out);
}